// round 10
// baseline (speedup 1.0000x reference)
#include <cuda_runtime.h>
#include <cuda_bf16.h>
#include <cstdint>

#define NBATCH 8
#define CDIM   256
#define TDIM   16384
#define DCODES 512
#define BT     128
#define NTHREADS 256
#define MARGIN 0.25f

// ---- smem byte layout ----
#define AK        18432                 // Ah one kchunk: 128 t x 144 B
#define OFF_B     73728                 // B double buffer (= 4*AK)
#define BSTAGE    18432                 // per stage: 128 codes x 64 c (144 B rows)
#define OFF_HN    110592                // float[512]
#define OFF_FIDX  112640                // int[128]
#define OFF_BQ    113152                // float[128]
#define OFF_FLAGS 113664                // int[128]
#define OFF_FLAGN 114176                // int
#define SMEM_BYTES 114192
// overlays in Ah+B region (dead post-mainloop): pb[128][16] u32 @0, ps @8192
// (dead after rescore); epilogue rowsT swizzled 64 KB @0

__device__ float g_hnorm[DCODES];
__device__ __align__(256) __nv_bfloat16 g_dh16[DCODES * CDIM];

// ---------------- helpers ----------------
__device__ __forceinline__ uint32_t smem_u32(const void* p) {
    uint32_t a;
    asm("{ .reg .u64 t; cvta.to.shared.u64 t, %1; cvt.u32.u64 %0, t; }" : "=r"(a) : "l"(p));
    return a;
}
__device__ __forceinline__ void ldmx4(uint32_t r[4], uint32_t addr) {
    asm volatile("ldmatrix.sync.aligned.m8n8.x4.shared.b16 {%0,%1,%2,%3}, [%4];"
                 : "=r"(r[0]), "=r"(r[1]), "=r"(r[2]), "=r"(r[3]) : "r"(addr));
}
__device__ __forceinline__ void mma16816(float c[4], const uint32_t a[4], const uint32_t b[2]) {
    asm volatile("mma.sync.aligned.m16n8k16.row.col.f32.bf16.bf16.f32 "
                 "{%0,%1,%2,%3}, {%4,%5,%6,%7}, {%8,%9}, {%0,%1,%2,%3};"
                 : "+f"(c[0]), "+f"(c[1]), "+f"(c[2]), "+f"(c[3])
                 : "r"(a[0]), "r"(a[1]), "r"(a[2]), "r"(a[3]), "r"(b[0]), "r"(b[1]));
}
#define CPA16(dst, src) \
    asm volatile("cp.async.cg.shared.global [%0], [%1], 16;" :: "r"(dst), "l"(src) : "memory")
#define CPA_COMMIT() asm volatile("cp.async.commit_group;" ::: "memory")
#define CPA_WAIT0()  asm volatile("cp.async.wait_group 0;" ::: "memory")
#define CPA_WAIT1()  asm volatile("cp.async.wait_group 1;" ::: "memory")

// order-preserving (score, idx) pack: larger packed = better score, tie -> smaller idx
__device__ __forceinline__ uint32_t pack_si(float v, int d) {
    uint32_t b = __float_as_uint(v);
    b ^= ((int32_t)b < 0) ? 0xFFFFFFFFu : 0x80000000u;
    return (b & ~511u) | (uint32_t)(511 - d);
}
__device__ __forceinline__ float unpack_s(uint32_t p) {
    uint32_t u = p & ~511u;
    uint32_t b = (u & 0x80000000u) ? (u ^ 0x80000000u) : ~u;
    return __uint_as_float(b);
}
__device__ __forceinline__ int unpack_i(uint32_t p) { return 511 - (int)(p & 511u); }

// swizzled rowsT offset (bytes): conflict-free for STS.128 along t and LDS.128 reads
__device__ __forceinline__ uint32_t rt_off(int c, int t) {
    return (uint32_t)(c * 512 + ((((t >> 2) ^ (c & 31)) << 4) | ((t & 3) << 2)));
}

// ---------------- merged prologue: hnorm + bf16-hi split ----------------
__global__ void vq_prep_kernel(const float* __restrict__ dict) {
    const int wid = threadIdx.x >> 5, lane = threadIdx.x & 31;
    const int d = blockIdx.x * 8 + wid;
    const float4* row = reinterpret_cast<const float4*>(dict + (size_t)d * CDIM);
    float4 a = row[lane * 2];
    float4 b = row[lane * 2 + 1];
    float s = a.x * a.x + a.y * a.y + a.z * a.z + a.w * a.w
            + b.x * b.x + b.y * b.y + b.z * b.z + b.w * b.w;
#pragma unroll
    for (int o = 16; o; o >>= 1) s += __shfl_xor_sync(0xffffffffu, s, o);
    if (lane == 0) g_hnorm[d] = 0.5f * s;

    __nv_bfloat162 h0 = __float22bfloat162_rn(make_float2(a.x, a.y));
    __nv_bfloat162 h1 = __float22bfloat162_rn(make_float2(a.z, a.w));
    __nv_bfloat162 h2 = __float22bfloat162_rn(make_float2(b.x, b.y));
    __nv_bfloat162 h3 = __float22bfloat162_rn(make_float2(b.z, b.w));
    uint4 v;
    v.x = *reinterpret_cast<uint32_t*>(&h0);
    v.y = *reinterpret_cast<uint32_t*>(&h1);
    v.z = *reinterpret_cast<uint32_t*>(&h2);
    v.w = *reinterpret_cast<uint32_t*>(&h3);
    reinterpret_cast<uint4*>(g_dh16 + (size_t)d * CDIM)[lane] = v;
}

// ---------------- main kernel ----------------
__global__ __launch_bounds__(NTHREADS, 2)
void vq_main_kernel(const float* __restrict__ inputs,
                    const float* __restrict__ dict,
                    float* __restrict__ out) {
    extern __shared__ float smem[];
    const uint32_t sbase = smem_u32(smem);
    char* smc = reinterpret_cast<char*>(smem);
    float* shn   = reinterpret_cast<float*>(smc + OFF_HN);
    int*   fidx  = reinterpret_cast<int*>(smc + OFF_FIDX);
    float* bq    = reinterpret_cast<float*>(smc + OFF_BQ);
    int*   flags = reinterpret_cast<int*>(smc + OFF_FLAGS);
    int*   flagn = reinterpret_cast<int*>(smc + OFF_FLAGN);

    const int tid = threadIdx.x;
    const int wid = tid >> 5, lane = tid & 31;
    const int wm = wid >> 2, wn = wid & 3;           // 2 x 4 warp grid
    const int n = blockIdx.x >> 7, tt0 = (blockIdx.x & 127) << 7;
    const size_t E = (size_t)NBATCH * CDIM * TDIM;

    if (tid == 0) *flagn = 0;
    shn[tid] = g_hnorm[tid];
    shn[tid + 256] = g_hnorm[tid + 256];

    // ===== A build: pipelined 8 x 16KB sub-slabs (32 c each), double-buffered =====
    {
        const int t = tid & 127, half = tid >> 7;    // 0..1
#define LOAD_SLAB(j_, buf_) do { \
    _Pragma("unroll") \
    for (int it = 0; it < 4; it++) { \
        int e = tid + it * 256; \
        int c = e >> 5, u = e & 31; \
        const float* src = inputs + ((size_t)(n * CDIM + (j_) * 32 + c)) * TDIM + tt0 + u * 4; \
        CPA16(sbase + OFF_B + (buf_) * 16384 + c * 512 + u * 16, src); \
    } \
    CPA_COMMIT(); \
} while (0)
        LOAD_SLAB(0, 0);
        for (int j = 0; j < 8; j++) {
            if (j < 7) { LOAD_SLAB(j + 1, (j + 1) & 1); CPA_WAIT1(); }
            else       { CPA_WAIT0(); }
            __syncthreads();
            const float* xsl = reinterpret_cast<const float*>(smc + OFF_B + (j & 1) * 16384);
#pragma unroll
            for (int i = 0; i < 4; i++) {
                int c = half * 16 + 4 * i;          // c within 32-c sub-slab
                float x0 = xsl[c * 128 + t];
                float x1 = xsl[(c + 1) * 128 + t];
                float x2 = xsl[(c + 2) * 128 + t];
                float x3 = xsl[(c + 3) * 128 + t];
                __nv_bfloat162 ha = __float22bfloat162_rn(make_float2(x0, x1));
                __nv_bfloat162 hb = __float22bfloat162_rn(make_float2(x2, x3));
                uint2 v;
                v.x = *reinterpret_cast<uint32_t*>(&ha);
                v.y = *reinterpret_cast<uint32_t*>(&hb);
                *reinterpret_cast<uint2*>(smc + (j >> 1) * AK + t * 144 +
                                          ((j & 1) * 32 + c) * 2) = v;
            }
            __syncthreads();
        }
    }

    // ================= mainloop (single pass: x_hi * W_hi) =================
    uint32_t b2[8], s2[8];                            // packed (score, idx) top-2
#pragma unroll
    for (int i = 0; i < 8; i++) { b2[i] = 0u; s2[i] = 0u; }

    const uint32_t aHrow = sbase + (uint32_t)((wm * 64 + (lane & 15)) * 144 + (lane >> 4) * 16);
    const uint32_t bRow  = (uint32_t)((wn * 32 + ((lane >> 4) & 1) * 8 + (lane & 7)) * 144 +
                                      ((lane >> 3) & 1) * 16);

#define STAGE_B(s_) do { \
    int nc_ = (s_) >> 2, kc_ = (s_) & 3; \
    uint32_t dstb = sbase + OFF_B + ((s_) & 1) * BSTAGE; \
    const __nv_bfloat16* sH = g_dh16 + (size_t)nc_ * 128 * CDIM + kc_ * 64; \
    _Pragma("unroll") \
    for (int it = 0; it < 4; it++) { \
        int j = tid + it * 256; int d = j >> 3, u = j & 7; \
        CPA16(dstb + d * 144 + u * 16, sH + (size_t)d * CDIM + u * 8); \
    } \
    CPA_COMMIT(); \
} while (0)

    STAGE_B(0); CPA_WAIT0(); __syncthreads();

    float acc[4][4][4];
    for (int s = 0; s < 16; s++) {
        const int nc = s >> 2, kc = s & 3;
        if (kc == 0) {
#pragma unroll
            for (int mt = 0; mt < 4; mt++)
#pragma unroll
                for (int nt = 0; nt < 4; nt++)
#pragma unroll
                    for (int e = 0; e < 4; e++) acc[mt][nt][e] = 0.f;
        }
        if (s < 15) STAGE_B(s + 1);

        const uint32_t aH = aHrow + kc * AK;
        const uint32_t bH = sbase + OFF_B + (s & 1) * BSTAGE + bRow;

#pragma unroll
        for (int ks = 0; ks < 4; ks++) {
            const uint32_t koff = ks * 32;
            uint32_t ah[4][4], bh[4][2];
#pragma unroll
            for (int mt = 0; mt < 4; mt++) ldmx4(ah[mt], aH + mt * 2304 + koff);
            {
                uint32_t tp[4];
                ldmx4(tp, bH + koff);        bh[0][0]=tp[0]; bh[0][1]=tp[1]; bh[1][0]=tp[2]; bh[1][1]=tp[3];
                ldmx4(tp, bH + 2304 + koff); bh[2][0]=tp[0]; bh[2][1]=tp[1]; bh[3][0]=tp[2]; bh[3][1]=tp[3];
            }
#pragma unroll
            for (int mt = 0; mt < 4; mt++)
#pragma unroll
                for (int nt = 0; nt < 4; nt++) mma16816(acc[mt][nt], ah[mt], bh[nt]);
        }

        if (kc == 3) {
            const int dbase = nc * 128 + wn * 32 + (lane & 3) * 2;
#pragma unroll
            for (int mt = 0; mt < 4; mt++) {
#pragma unroll
                for (int rh = 0; rh < 2; rh++) {
                    const int li = mt * 2 + rh;
                    uint32_t b_ = b2[li], s_ = s2[li];
#pragma unroll
                    for (int nt = 0; nt < 4; nt++) {
#pragma unroll
                        for (int cc = 0; cc < 2; cc++) {
                            const int d = dbase + nt * 8 + cc;
                            float v = acc[mt][nt][rh * 2 + cc] - shn[d];
                            uint32_t p = pack_si(v, d);
                            if (p > b_) { s_ = b_; b_ = p; }
                            else if (p > s_) s_ = p;
                        }
                    }
                    b2[li] = b_; s2[li] = s_;
                }
            }
        }
        CPA_WAIT0();
        __syncthreads();
    }

    // ================= per-group top-2 publish (packed) =================
    uint32_t* pb = reinterpret_cast<uint32_t*>(smem);      // [128][16]
    uint32_t* ps = pb + 2048;                              // [128][16]
    {
        const int slot = wn * 4 + (lane & 3);
#pragma unroll
        for (int mt = 0; mt < 4; mt++)
#pragma unroll
            for (int rh = 0; rh < 2; rh++) {
                const int li = mt * 2 + rh;
                const int t = wm * 64 + mt * 16 + (lane >> 2) + rh * 8;
                pb[t * 16 + slot] = b2[li];
                ps[t * 16 + slot] = s2[li];
            }
    }
    __syncthreads();

    // ================= approx argmax + candidate flagging =================
    if (tid < BT) {
        uint32_t B = 0u;
#pragma unroll 4
        for (int q = 0; q < 16; q++) B = max(B, pb[tid * 16 + q]);
        const int I = unpack_i(B);
        const float Bf = unpack_s(B);
        int ncand = 0;
#pragma unroll 4
        for (int k = 0; k < 32; k++) {
            uint32_t p = (k < 16) ? pb[tid * 16 + k] : ps[tid * 16 + (k - 16)];
            if (unpack_s(p) > Bf - MARGIN && unpack_i(p) != I) ncand++;
        }
        fidx[tid] = I; bq[tid] = Bf;
        if (ncand) { int p = atomicAdd(flagn, 1); flags[p] = tid; }
    }
    __syncthreads();

    // ================= exact fp32 rescore of ALL in-margin candidates =================
    {
        const int nf = *flagn;
        for (int e = wid; e < nf; e += 8) {
            const int q = flags[e];
            const float B = bq[q];
            const float* xp = inputs + ((size_t)n * CDIM) * TDIM + tt0 + q;
            float xr[8];
#pragma unroll
            for (int j = 0; j < 8; j++) xr[j] = xp[(size_t)(lane + 32 * j) * TDIM];
            float bestE = -3.0e38f; int bestI = 0x3fffffff;
            for (int k = 0; k < 32; k++) {
                uint32_t pk = (k < 16) ? pb[q * 16 + k] : ps[q * 16 + (k - 16)];
                if (unpack_s(pk) > B - MARGIN) {
                    const int i2 = unpack_i(pk);
                    const float* drow = dict + (size_t)i2 * CDIM;
                    float p = 0.f;
#pragma unroll
                    for (int j = 0; j < 8; j++) p += xr[j] * drow[lane + 32 * j];
#pragma unroll
                    for (int o = 16; o; o >>= 1) p += __shfl_xor_sync(0xffffffffu, p, o);
                    float c = p - shn[i2];
                    if (c > bestE || (c == bestE && i2 < bestI)) { bestE = c; bestI = i2; }
                }
            }
            if (lane == 0) fidx[q] = bestI;
        }
    }
    __syncthreads();

    if (tid < BT)
        out[2 * E + (size_t)n * TDIM + tt0 + tid] = (float)fidx[tid];

    // ================= swizzled conflict-free epilogue: 2 c-halves =================
    {
        float* out_e = out;
        float* out_p = out + E;
        for (int h = 0; h < 2; h++) {
            __syncthreads();   // previous half reads done / rescore tables dead
#pragma unroll
            for (int g4 = 0; g4 < 4; g4++) {
                const int g = wid + 8 * g4;
                const float* r0 = dict + (size_t)fidx[4 * g    ] * CDIM + h * 128;
                const float* r1 = dict + (size_t)fidx[4 * g + 1] * CDIM + h * 128;
                const float* r2 = dict + (size_t)fidx[4 * g + 2] * CDIM + h * 128;
                const float* r3 = dict + (size_t)fidx[4 * g + 3] * CDIM + h * 128;
#pragma unroll
                for (int cc = 0; cc < 4; cc++) {
                    const int cl = cc * 32 + lane;
                    float4 v = make_float4(r0[cl], r1[cl], r2[cl], r3[cl]);
                    *reinterpret_cast<float4*>(smc + rt_off(cl, 4 * g)) = v;
                }
            }
            __syncthreads();
#pragma unroll
            for (int j = 0; j < 16; j++) {
                const int cl = wid + 8 * j;
                float4 v = *reinterpret_cast<const float4*>(smc + rt_off(cl, 4 * lane));
                size_t o = ((size_t)n * CDIM + h * 128 + cl) * TDIM + tt0 + 4 * lane;
                *reinterpret_cast<float4*>(out_e + o) = v;
                *reinterpret_cast<float4*>(out_p + o) = v;
            }
        }
    }
}

// ---------------------------------------------------------------------------
extern "C" void kernel_launch(void* const* d_in, const int* in_sizes, int n_in,
                              void* d_out, int out_size) {
    const float* inputs = (const float*)d_in[0];
    const float* dict   = (const float*)d_in[1];
    float* out = (float*)d_out;

    cudaFuncSetAttribute(vq_main_kernel,
                         cudaFuncAttributeMaxDynamicSharedMemorySize, SMEM_BYTES);

    vq_prep_kernel<<<64, 256>>>(dict);
    vq_main_kernel<<<(NBATCH * TDIM) / BT, NTHREADS, SMEM_BYTES>>>(inputs, dict, out);
}